// round 14
// baseline (speedup 1.0000x reference)
#include <cuda_runtime.h>
#include <cuda_bf16.h>
#include <cstdint>

#define NN  512
#define GG  60
#define KKN 13

// ---------------- scratch (device globals; allocation-free) ----------------
__device__ float g_E [GG * NN * 32];                   // conv_out result fp32
// split activations (bf16 hi/lo), layout [g, n, C]
__device__ __nv_bfloat16 g_Xh[GG * NN * 32],            g_Xl[GG * NN * 32];
__device__ __nv_bfloat16 g_Hh[(size_t)GG * NN * 256],   g_Hl[(size_t)GG * NN * 256];
__device__ __nv_bfloat16 g_Rh[(size_t)GG * NN * 512],   g_Rl[(size_t)GG * NN * 512];
__device__ __nv_bfloat16 g_H2h[(size_t)GG * NN * 256],  g_H2l[(size_t)GG * NN * 256];
// weight chunk images (bf16 hi/lo): [o_blk][chunk t][row o (NM)][32]
__device__ __nv_bfloat16 g_Bh_in [256 * 32  * KKN], g_Bl_in [256 * 32  * KKN];
__device__ __nv_bfloat16 g_Bh_r1 [512 * 256 * KKN], g_Bl_r1 [512 * 256 * KKN];
__device__ __nv_bfloat16 g_Bh_r2 [256 * 512 * KKN], g_Bl_r2 [256 * 512 * KKN];
__device__ __nv_bfloat16 g_Bh_out[32  * 256 * KKN], g_Bl_out[32  * 256 * KKN];

// ---------------- helpers ----------------
__device__ __forceinline__ uint32_t smem_u32(const void* p) {
    uint32_t a;
    asm("{ .reg .u64 t; cvta.to.shared.u64 t, %1; cvt.u32.u64 %0, t; }" : "=r"(a) : "l"(p));
    return a;
}
__device__ __forceinline__ uint32_t pk2(float x, float y) {
    __nv_bfloat162 t = __floats2bfloat162_rn(x, y);
    return *reinterpret_cast<uint32_t*>(&t);
}
// 64B-row swizzle: permute 16B chunk index by (row>>1)&3 -> conflict-free ldmatrix
__device__ __forceinline__ uint32_t swz(int row, int chunk) {
    return (uint32_t)(row * 64 + ((chunk ^ ((row >> 1) & 3)) * 16));
}
__device__ __forceinline__ void ldsm4(uint32_t a, uint32_t r[4]) {
    asm volatile("ldmatrix.sync.aligned.m8n8.x4.shared.b16 {%0,%1,%2,%3}, [%4];"
        : "=r"(r[0]), "=r"(r[1]), "=r"(r[2]), "=r"(r[3]) : "r"(a));
}
__device__ __forceinline__ void mma_bf(float d[4], const uint32_t a[4], const uint32_t b[2]) {
    asm volatile("mma.sync.aligned.m16n8k16.row.col.f32.bf16.bf16.f32 "
        "{%0,%1,%2,%3}, {%4,%5,%6,%7}, {%8,%9}, {%0,%1,%2,%3};"
        : "+f"(d[0]), "+f"(d[1]), "+f"(d[2]), "+f"(d[3])
        : "r"(a[0]), "r"(a[1]), "r"(a[2]), "r"(a[3]), "r"(b[0]), "r"(b[1]));
}
#define CP_ASYNC16(saddr, gptr) \
    asm volatile("cp.async.cg.shared.global [%0], [%1], 16;" :: "r"(saddr), "l"(gptr) : "memory")
#define CP_COMMIT()  asm volatile("cp.async.commit_group;" ::: "memory")
#define CP_WAIT0()   asm volatile("cp.async.wait_group 0;" ::: "memory")
#define CP_WAIT1()   asm volatile("cp.async.wait_group 1;" ::: "memory")

// ---------------- fused prep: feats split + all four weight splits ----------------
__global__ void k_prep(const float* __restrict__ feats,
                       const float* __restrict__ W0, const float* __restrict__ W1,
                       const float* __restrict__ W2, const float* __restrict__ W3) {
    int idx = blockIdx.x * blockDim.x + threadIdx.x;
    const int fTot = GG * NN * 32;
    if (idx < fTot) {
        int g = idx / (NN * 32);
        int r = idx % (NN * 32);
        int n = r / 32, c = r % 32;
        float v = feats[(n * 32 + c) * GG + g];
        __nv_bfloat16 h = __float2bfloat16(v);
        g_Xh[idx] = h;
        g_Xl[idx] = __float2bfloat16(v - __bfloat162float(h));
        return;
    }
    int wi = idx - fTot;
    const int s0 = 256 * 32 * KKN;          // in
    const int s1 = 512 * 256 * KKN;         // r1
    const int s2 = 256 * 512 * KKN;         // r2
    const int s3 = 32 * 256 * KKN;          // out
    const float* W; __nv_bfloat16 *Wh, *Wl; int C, NM, li;
    if (wi < s0)                { W = W0; Wh = g_Bh_in;  Wl = g_Bl_in;  C = 32;  NM = 128; li = wi; }
    else if (wi < s0 + s1)      { W = W1; Wh = g_Bh_r1;  Wl = g_Bl_r1;  C = 256; NM = 128; li = wi - s0; }
    else if (wi < s0 + s1 + s2) { W = W2; Wh = g_Bh_r2;  Wl = g_Bl_r2;  C = 512; NM = 128; li = wi - s0 - s1; }
    else if (wi < s0 + s1 + s2 + s3)
                                { W = W3; Wh = g_Bh_out; Wl = g_Bl_out; C = 256; NM = 32;  li = wi - s0 - s1 - s2; }
    else return;
    const int CK = C * KKN;
    int o = li / CK, ck = li % CK;
    int k = ck / C, c = ck % C;
    float v = W[(o * C + c) * KKN + k];
    __nv_bfloat16 h = __float2bfloat16(v);
    int T = CK / 32, t = ck / 32, j = ck % 32;
    int ob = o / NM, row = o % NM;
    size_t di = ((size_t)(ob * T + t) * NM + row) * 32 + j;
    Wh[di] = h;
    Wl[di] = __float2bfloat16(v - __bfloat162float(h));
}

// ---------------- bf16x3 mma.sync gather-GEMM (pre-split operands) ----------------
// D[n,o] = sum_{k,c} X[nei[g,k]][n][c] * W[o][k*C+c] ; epilogue per flags
// CTA tile: MTILE x NM, 4 warps (128 threads), 3 CTAs/SM.
// 3-stage cp.async pipeline (2-chunk copy lookahead), 1 sync/chunk.
template <int C, int O, int MTILE, int NM, bool RELU, bool WF32, bool RRES, bool WSPLIT>
__global__ void __launch_bounds__(128, 3)
k_gemm(const __nv_bfloat16* __restrict__ Ah, const __nv_bfloat16* __restrict__ Al,
       const __nv_bfloat16* __restrict__ Bhg, const __nv_bfloat16* __restrict__ Blg,
       const float* __restrict__ b, const int* __restrict__ nei,
       float* __restrict__ outF,
       const __nv_bfloat16* __restrict__ resH, const __nv_bfloat16* __restrict__ resL,
       __nv_bfloat16* __restrict__ outH, __nv_bfloat16* __restrict__ outL) {
    constexpr int NTHR = 128;
    constexpr int NWARP = 4;
    constexpr int CK  = C * KKN;
    constexpr int T   = CK / 32;
    constexpr int S   = 3;              // pipeline stages
    constexpr int WGN = (NM / 32 < NWARP) ? NM / 32 : NWARP;   // warps along o
    constexpr int WGM = NWARP / WGN;    // warps along n
    constexpr int WTM = MTILE / WGM;    // warp tile m
    constexpr int MT  = WTM / 16;
    static_assert(WTM >= 16, "warp tile too small");
    constexpr int NT  = 4;              // warp tile n = 32
    constexpr int AREG = MTILE * 64;    // one A matrix region (MTILE rows x 64B, swizzled)
    constexpr int BREG = NM * 64;
    constexpr int SSZ  = 2 * AREG + 2 * BREG;

    extern __shared__ char smem[];
    __shared__ int   s_nei[KKN];
    __shared__ float s_bias[NM];

    const int tid = threadIdx.x;
    const int g   = blockIdx.z;
    const int n0  = blockIdx.x * MTILE;
    const int o0  = blockIdx.y * NM;
    const uint32_t sb = smem_u32(smem);

    if (tid < KKN) s_nei[tid] = nei[g * KKN + tid];
    for (int i = tid; i < NM; i += NTHR) s_bias[i] = b[o0 + i];
    __syncthreads();

    const int lane  = tid & 31;
    const int warp  = tid >> 5;
    const int m_off = (warp % WGM) * WTM;
    const int o_off = (warp / WGM) * 32;

    float acc[MT][NT][4];
    #pragma unroll
    for (int mt = 0; mt < MT; mt++)
        #pragma unroll
        for (int nt = 0; nt < NT; nt++)
            #pragma unroll
            for (int q = 0; q < 4; q++) acc[mt][nt][q] = 0.0f;

    auto copyAB = [&](int t, int s) {
        int k = (t * 32) / C, c0 = (t * 32) % C;
        size_t abase = ((size_t)(s_nei[k] * NN + n0)) * C + c0;
        uint32_t as = sb + s * SSZ;
        constexpr int NA = MTILE * 4;           // 16B transfers per A matrix
        #pragma unroll
        for (int i = 0; i < (NA + NTHR - 1) / NTHR; i++) {
            int lin = tid + i * NTHR;
            if ((NA % NTHR) && lin >= NA) break;
            int row = lin >> 2, seg = lin & 3;
            uint32_t sa = as + swz(row, seg);
            size_t go = abase + (size_t)row * C + seg * 8;
            CP_ASYNC16(sa, Ah + go);
            CP_ASYNC16(sa + AREG, Al + go);
        }
        const __nv_bfloat16* srch = Bhg + (size_t)(blockIdx.y * T + t) * NM * 32;
        const __nv_bfloat16* srcl = Blg + (size_t)(blockIdx.y * T + t) * NM * 32;
        uint32_t bs = sb + s * SSZ + 2 * AREG;
        constexpr int NB = NM * 4;              // 16B transfers per B matrix
        #pragma unroll
        for (int i = 0; i < (NB + NTHR - 1) / NTHR; i++) {
            int lin = tid + i * NTHR;
            if ((NB % NTHR) && lin >= NB) break;
            int row = lin >> 2, seg = lin & 3;
            uint32_t sa = bs + swz(row, seg);
            CP_ASYNC16(sa, srch + lin * 8);
            CP_ASYNC16(sa + BREG, srcl + lin * 8);
        }
        CP_COMMIT();
    };

    auto compute = [&](int s) {
        uint32_t aB = sb + s * SSZ;
        uint32_t bB = aB + 2 * AREG;
        #pragma unroll
        for (int kh = 0; kh < 2; kh++) {
            uint32_t ah[MT][4], al[MT][4];
            uint32_t bh[NT][2], bl[NT][2];
            #pragma unroll
            for (int mt = 0; mt < MT; mt++) {
                int row = m_off + mt * 16 + (lane & 15);
                uint32_t ad = aB + swz(row, kh * 2 + (lane >> 4));
                ldsm4(ad, ah[mt]);
                ldsm4(ad + AREG, al[mt]);
            }
            #pragma unroll
            for (int p = 0; p < 2; p++) {
                int row = o_off + p * 16 + ((lane >> 4) & 1) * 8 + (lane & 7);
                uint32_t bd = bB + swz(row, kh * 2 + ((lane >> 3) & 1));
                uint32_t r[4];
                ldsm4(bd, r);
                bh[p * 2][0] = r[0]; bh[p * 2][1] = r[1];
                bh[p * 2 + 1][0] = r[2]; bh[p * 2 + 1][1] = r[3];
                ldsm4(bd + BREG, r);
                bl[p * 2][0] = r[0]; bl[p * 2][1] = r[1];
                bl[p * 2 + 1][0] = r[2]; bl[p * 2 + 1][1] = r[3];
            }
            // term-major: same-accumulator reuse distance = MT*NT mmas
            #pragma unroll
            for (int mt = 0; mt < MT; mt++)
                #pragma unroll
                for (int nt = 0; nt < NT; nt++) mma_bf(acc[mt][nt], ah[mt], bh[nt]);
            #pragma unroll
            for (int mt = 0; mt < MT; mt++)
                #pragma unroll
                for (int nt = 0; nt < NT; nt++) mma_bf(acc[mt][nt], al[mt], bh[nt]);
            #pragma unroll
            for (int mt = 0; mt < MT; mt++)
                #pragma unroll
                for (int nt = 0; nt < NT; nt++) mma_bf(acc[mt][nt], ah[mt], bl[nt]);
        }
    };

    // 3-stage cp.async pipeline, one __syncthreads per chunk.
    // At iter t: wait_group 1 -> copy(t) landed (copy(t+1) may still fly);
    // sync publishes stage t%3 and proves compute(t-1) (stage (t+2)%3) done;
    // then issue copy(t+2) with two full chunks of latency cover.
    copyAB(0, 0);
    if (T > 1) copyAB(1, 1);
    for (int t = 0; t < T; t++) {
        int s = t % S;
        if (t + 1 < T) { CP_WAIT1(); } else { CP_WAIT0(); }
        __syncthreads();
        if (t + 2 < T) copyAB(t + 2, (t + 2) % S);
        compute(s);
    }

    // epilogue (acc regs only)
    #pragma unroll
    for (int mt = 0; mt < MT; mt++) {
        int r0 = n0 + m_off + mt * 16 + (lane >> 2);
        #pragma unroll
        for (int nt = 0; nt < NT; nt++) {
            int cl = o_off + nt * 8 + (lane & 3) * 2;
            float b0v = s_bias[cl], b1v = s_bias[cl + 1];
            #pragma unroll
            for (int q = 0; q < 2; q++) {
                int r = r0 + q * 8;
                float vx = acc[mt][nt][q * 2 + 0] + b0v;
                float vy = acc[mt][nt][q * 2 + 1] + b1v;
                if (RELU) { vx = fmaxf(vx, 0.f); vy = fmaxf(vy, 0.f); }
                size_t ei = ((size_t)g * NN + r) * O + o0 + cl;
                if (RRES) {
                    __nv_bfloat162 ph = *(const __nv_bfloat162*)(resH + ei);
                    __nv_bfloat162 pl = *(const __nv_bfloat162*)(resL + ei);
                    vx += __bfloat162float(ph.x) + __bfloat162float(pl.x);
                    vy += __bfloat162float(ph.y) + __bfloat162float(pl.y);
                }
                if (WF32) *(float2*)(outF + ei) = make_float2(vx, vy);
                if (WSPLIT) {
                    float hx = __bfloat162float(__float2bfloat16(vx));
                    float hy = __bfloat162float(__float2bfloat16(vy));
                    *(uint32_t*)(outH + ei) = pk2(hx, hy);
                    *(uint32_t*)(outL + ei) = pk2(vx - hx, vy - hy);
                }
            }
        }
    }
}

// ---------------- epilogue: residual + mean + norms + output ----------------
// out layout: [ feats_inv (N*32) | feats_eqv (N*32*G) ]
__global__ void k_final(const float* __restrict__ feats, float* __restrict__ out) {
    const int n   = blockIdx.x;
    const int tid = threadIdx.x;   // 256 threads
    __shared__ float s_eqv[32][GG];
    __shared__ float s_inv[32];
    __shared__ float s_ng[GG];
    __shared__ float s_ninv;

    for (int idx = tid; idx < 32 * GG; idx += 256) {
        int c = idx / GG;
        int g = idx % GG;
        s_eqv[c][g] = g_E[((size_t)g * NN + n) * 32 + c] + feats[(n * 32 + c) * GG + g];
    }
    __syncthreads();

    if (tid < 32) {
        float sum = 0.0f;
        #pragma unroll 4
        for (int g = 0; g < GG; g++) sum += s_eqv[tid][g];
        s_inv[tid] = sum * (1.0f / GG);
    }
    if (tid >= 64 && tid < 64 + GG) {
        int g = tid - 64;
        float q = 0.0f;
        #pragma unroll
        for (int c = 0; c < 32; c++) { float v = s_eqv[c][g]; q += v * v; }
        s_ng[g] = fmaxf(sqrtf(q), 1e-4f);
    }
    __syncthreads();
    if (tid == 0) {
        float q = 0.0f;
        #pragma unroll
        for (int c = 0; c < 32; c++) q += s_inv[c] * s_inv[c];
        s_ninv = fmaxf(sqrtf(q), 1e-4f);
    }
    __syncthreads();

    if (tid < 32) out[n * 32 + tid] = s_inv[tid] / s_ninv;
    for (int idx = tid; idx < 32 * GG; idx += 256) {
        int c = idx / GG;
        int g = idx % GG;
        out[NN * 32 + (n * 32 + c) * GG + g] = s_eqv[c][g] / s_ng[g];
    }
}

// ---------------- launch (single stream, linear graph) ----------------
extern "C" void kernel_launch(void* const* d_in, const int* in_sizes, int n_in,
                              void* d_out, int out_size) {
    const float* feats = (const float*)d_in[0];
    const int*   nei   = (const int*)  d_in[1];
    const float* W_in  = (const float*)d_in[2];
    const float* b_in  = (const float*)d_in[3];
    const float* W_r1  = (const float*)d_in[4];
    const float* b_r1  = (const float*)d_in[5];
    const float* W_r2  = (const float*)d_in[6];
    const float* b_r2  = (const float*)d_in[7];
    const float* W_out = (const float*)d_in[8];
    const float* b_out = (const float*)d_in[9];
    float* out = (float*)d_out;

    void *pE, *pXh, *pXl, *pHh, *pHl, *pRh, *pRl, *pH2h, *pH2l;
    void *pBh_in, *pBl_in, *pBh_r1, *pBl_r1, *pBh_r2, *pBl_r2, *pBh_out, *pBl_out;
    cudaGetSymbolAddress(&pE,  g_E);
    cudaGetSymbolAddress(&pXh, g_Xh);  cudaGetSymbolAddress(&pXl, g_Xl);
    cudaGetSymbolAddress(&pHh, g_Hh);  cudaGetSymbolAddress(&pHl, g_Hl);
    cudaGetSymbolAddress(&pRh, g_Rh);  cudaGetSymbolAddress(&pRl, g_Rl);
    cudaGetSymbolAddress(&pH2h, g_H2h); cudaGetSymbolAddress(&pH2l, g_H2l);
    cudaGetSymbolAddress(&pBh_in,  g_Bh_in);   cudaGetSymbolAddress(&pBl_in,  g_Bl_in);
    cudaGetSymbolAddress(&pBh_r1,  g_Bh_r1);   cudaGetSymbolAddress(&pBl_r1,  g_Bl_r1);
    cudaGetSymbolAddress(&pBh_r2,  g_Bh_r2);   cudaGetSymbolAddress(&pBl_r2,  g_Bl_r2);
    cudaGetSymbolAddress(&pBh_out, g_Bh_out);  cudaGetSymbolAddress(&pBl_out, g_Bl_out);

    const int SMA = 3 * (2 * 32 * 64 + 2 * 128 * 64);   // 61440 (32x128 tiles, 3 stages)
    const int SMO = 3 * (2 * 128 * 64 + 2 * 32 * 64);   // 61440 (128x32 tile, 3 stages)
    cudaFuncSetAttribute((const void*)k_gemm<32, 256, 32, 128, false, false, false, true>,
                         cudaFuncAttributeMaxDynamicSharedMemorySize, SMA);
    cudaFuncSetAttribute((const void*)k_gemm<256, 512, 32, 128, true, false, false, true>,
                         cudaFuncAttributeMaxDynamicSharedMemorySize, SMA);
    cudaFuncSetAttribute((const void*)k_gemm<512, 256, 32, 128, false, false, true, true>,
                         cudaFuncAttributeMaxDynamicSharedMemorySize, SMA);
    cudaFuncSetAttribute((const void*)k_gemm<256, 32, 128, 32, false, true, false, false>,
                         cudaFuncAttributeMaxDynamicSharedMemorySize, SMO);

    // 1. fused prep: feats split + all four weight splits (one launch)
    {
        int total = GG * NN * 32
                  + (256 * 32 + 512 * 256 + 256 * 512 + 32 * 256) * KKN;
        k_prep<<<(total + 255) / 256, 256>>>(feats, W_in, W_r1, W_r2, W_out);
    }
    // 2. in: Hh/Hl = split(comb(X, W_in) + b_in)
    k_gemm<32, 256, 32, 128, false, false, false, true><<<dim3(16, 2, GG), 128, SMA>>>(
        (const __nv_bfloat16*)pXh, (const __nv_bfloat16*)pXl,
        (const __nv_bfloat16*)pBh_in, (const __nv_bfloat16*)pBl_in,
        b_in, nei, nullptr, nullptr, nullptr,
        (__nv_bfloat16*)pHh, (__nv_bfloat16*)pHl);
    // 3. r1: Rh/Rl = split(relu(comb(H, W_r1) + b_r1))
    k_gemm<256, 512, 32, 128, true, false, false, true><<<dim3(16, 4, GG), 128, SMA>>>(
        (const __nv_bfloat16*)pHh, (const __nv_bfloat16*)pHl,
        (const __nv_bfloat16*)pBh_r1, (const __nv_bfloat16*)pBl_r1,
        b_r1, nei, nullptr, nullptr, nullptr,
        (__nv_bfloat16*)pRh, (__nv_bfloat16*)pRl);
    // 4. r2: H2h/H2l = split((Hh+Hl) + comb(R, W_r2) + b_r2)
    k_gemm<512, 256, 32, 128, false, false, true, true><<<dim3(16, 2, GG), 128, SMA>>>(
        (const __nv_bfloat16*)pRh, (const __nv_bfloat16*)pRl,
        (const __nv_bfloat16*)pBh_r2, (const __nv_bfloat16*)pBl_r2,
        b_r2, nei, nullptr,
        (const __nv_bfloat16*)pHh, (const __nv_bfloat16*)pHl,
        (__nv_bfloat16*)pH2h, (__nv_bfloat16*)pH2l);
    // 5. out: E = comb(H2, W_out) + b_out (fp32)
    k_gemm<256, 32, 128, 32, false, true, false, false><<<dim3(4, 1, GG), 128, SMO>>>(
        (const __nv_bfloat16*)pH2h, (const __nv_bfloat16*)pH2l,
        (const __nv_bfloat16*)pBh_out, (const __nv_bfloat16*)pBl_out,
        b_out, nei, (float*)pE, nullptr, nullptr, nullptr, nullptr);
    // 6. final: residual + mean + norms
    k_final<<<NN, 256>>>(feats, out);
}

// round 15
// speedup vs baseline: 1.1729x; 1.1729x over previous
#include <cuda_runtime.h>
#include <cuda_bf16.h>
#include <cstdint>

#define NN  512
#define GG  60
#define KKN 13

// ---------------- scratch (device globals; allocation-free) ----------------
__device__ float g_E [GG * NN * 32];                   // conv_out result fp32
// split activations (bf16 hi/lo), layout [g, n, C]
__device__ __nv_bfloat16 g_Xh[GG * NN * 32],            g_Xl[GG * NN * 32];
__device__ __nv_bfloat16 g_Hh[(size_t)GG * NN * 256],   g_Hl[(size_t)GG * NN * 256];
__device__ __nv_bfloat16 g_Rh[(size_t)GG * NN * 512],   g_Rl[(size_t)GG * NN * 512];
__device__ __nv_bfloat16 g_H2h[(size_t)GG * NN * 256],  g_H2l[(size_t)GG * NN * 256];
// weight chunk images (bf16 hi/lo): [o_blk][chunk t][row o (NM)][32]
__device__ __nv_bfloat16 g_Bh_in [256 * 32  * KKN], g_Bl_in [256 * 32  * KKN];
__device__ __nv_bfloat16 g_Bh_r1 [512 * 256 * KKN], g_Bl_r1 [512 * 256 * KKN];
__device__ __nv_bfloat16 g_Bh_r2 [256 * 512 * KKN], g_Bl_r2 [256 * 512 * KKN];
__device__ __nv_bfloat16 g_Bh_out[32  * 256 * KKN], g_Bl_out[32  * 256 * KKN];

// ---------------- helpers ----------------
__device__ __forceinline__ uint32_t smem_u32(const void* p) {
    uint32_t a;
    asm("{ .reg .u64 t; cvta.to.shared.u64 t, %1; cvt.u32.u64 %0, t; }" : "=r"(a) : "l"(p));
    return a;
}
__device__ __forceinline__ uint32_t pk2(float x, float y) {
    __nv_bfloat162 t = __floats2bfloat162_rn(x, y);
    return *reinterpret_cast<uint32_t*>(&t);
}
// 64B-row swizzle: permute 16B chunk index by (row>>1)&3 -> conflict-free ldmatrix
__device__ __forceinline__ uint32_t swz(int row, int chunk) {
    return (uint32_t)(row * 64 + ((chunk ^ ((row >> 1) & 3)) * 16));
}
__device__ __forceinline__ void ldsm4(uint32_t a, uint32_t r[4]) {
    asm volatile("ldmatrix.sync.aligned.m8n8.x4.shared.b16 {%0,%1,%2,%3}, [%4];"
        : "=r"(r[0]), "=r"(r[1]), "=r"(r[2]), "=r"(r[3]) : "r"(a));
}
__device__ __forceinline__ void mma_bf(float d[4], const uint32_t a[4], const uint32_t b[2]) {
    asm volatile("mma.sync.aligned.m16n8k16.row.col.f32.bf16.bf16.f32 "
        "{%0,%1,%2,%3}, {%4,%5,%6,%7}, {%8,%9}, {%0,%1,%2,%3};"
        : "+f"(d[0]), "+f"(d[1]), "+f"(d[2]), "+f"(d[3])
        : "r"(a[0]), "r"(a[1]), "r"(a[2]), "r"(a[3]), "r"(b[0]), "r"(b[1]));
}
#define CP_ASYNC16(saddr, gptr) \
    asm volatile("cp.async.cg.shared.global [%0], [%1], 16;" :: "r"(saddr), "l"(gptr) : "memory")
#define CP_COMMIT()  asm volatile("cp.async.commit_group;" ::: "memory")
#define CP_WAIT0()   asm volatile("cp.async.wait_group 0;" ::: "memory")

// ---------------- fused prep: feats split + all four weight splits ----------------
__global__ void k_prep(const float* __restrict__ feats,
                       const float* __restrict__ W0, const float* __restrict__ W1,
                       const float* __restrict__ W2, const float* __restrict__ W3) {
    int idx = blockIdx.x * blockDim.x + threadIdx.x;
    const int fTot = GG * NN * 32;
    if (idx < fTot) {
        int g = idx / (NN * 32);
        int r = idx % (NN * 32);
        int n = r / 32, c = r % 32;
        float v = feats[(n * 32 + c) * GG + g];
        __nv_bfloat16 h = __float2bfloat16(v);
        g_Xh[idx] = h;
        g_Xl[idx] = __float2bfloat16(v - __bfloat162float(h));
        return;
    }
    int wi = idx - fTot;
    const int s0 = 256 * 32 * KKN;          // in
    const int s1 = 512 * 256 * KKN;         // r1
    const int s2 = 256 * 512 * KKN;         // r2
    const int s3 = 32 * 256 * KKN;          // out
    const float* W; __nv_bfloat16 *Wh, *Wl; int C, NM, li;
    if (wi < s0)                { W = W0; Wh = g_Bh_in;  Wl = g_Bl_in;  C = 32;  NM = 128; li = wi; }
    else if (wi < s0 + s1)      { W = W1; Wh = g_Bh_r1;  Wl = g_Bl_r1;  C = 256; NM = 128; li = wi - s0; }
    else if (wi < s0 + s1 + s2) { W = W2; Wh = g_Bh_r2;  Wl = g_Bl_r2;  C = 512; NM = 128; li = wi - s0 - s1; }
    else if (wi < s0 + s1 + s2 + s3)
                                { W = W3; Wh = g_Bh_out; Wl = g_Bl_out; C = 256; NM = 32;  li = wi - s0 - s1 - s2; }
    else return;
    const int CK = C * KKN;
    int o = li / CK, ck = li % CK;
    int k = ck / C, c = ck % C;
    float v = W[(o * C + c) * KKN + k];
    __nv_bfloat16 h = __float2bfloat16(v);
    int T = CK / 32, t = ck / 32, j = ck % 32;
    int ob = o / NM, row = o % NM;
    size_t di = ((size_t)(ob * T + t) * NM + row) * 32 + j;
    Wh[di] = h;
    Wl[di] = __float2bfloat16(v - __bfloat162float(h));
}

// ---------------- bf16x3 mma.sync gather-GEMM (pre-split operands) ----------------
// D[n,o] = sum_{k,c} X[nei[g,k]][n][c] * W[o][k*C+c] ; epilogue per flags
// CTA tile: MTILE x NM, 4 warps (128 threads), MAXB CTAs/SM.
// 2-stage cp.async pipeline, 1 sync/chunk. (Per-layer configs race-tested R10/R13.)
template <int C, int O, int MTILE, int NM, int MAXB, bool RELU, bool WF32, bool RRES, bool WSPLIT>
__global__ void __launch_bounds__(128, MAXB)
k_gemm(const __nv_bfloat16* __restrict__ Ah, const __nv_bfloat16* __restrict__ Al,
       const __nv_bfloat16* __restrict__ Bhg, const __nv_bfloat16* __restrict__ Blg,
       const float* __restrict__ b, const int* __restrict__ nei,
       float* __restrict__ outF,
       const __nv_bfloat16* __restrict__ resH, const __nv_bfloat16* __restrict__ resL,
       __nv_bfloat16* __restrict__ outH, __nv_bfloat16* __restrict__ outL) {
    constexpr int NTHR = 128;
    constexpr int NWARP = 4;
    constexpr int CK  = C * KKN;
    constexpr int T   = CK / 32;
    constexpr int WGN = (NM / 32 < NWARP) ? NM / 32 : NWARP;   // warps along o
    constexpr int WGM = NWARP / WGN;    // warps along n
    constexpr int WTM = MTILE / WGM;    // warp tile m
    constexpr int MT  = WTM / 16;
    static_assert(WTM >= 16, "warp tile too small");
    constexpr int NT  = 4;              // warp tile n = 32
    constexpr int AREG = MTILE * 64;    // one A matrix region (MTILE rows x 64B, swizzled)
    constexpr int BREG = NM * 64;
    constexpr int SSZ  = 2 * AREG + 2 * BREG;

    extern __shared__ char smem[];
    __shared__ int   s_nei[KKN];
    __shared__ float s_bias[NM];

    const int tid = threadIdx.x;
    const int g   = blockIdx.z;
    const int n0  = blockIdx.x * MTILE;
    const int o0  = blockIdx.y * NM;
    const uint32_t sb = smem_u32(smem);

    if (tid < KKN) s_nei[tid] = nei[g * KKN + tid];
    for (int i = tid; i < NM; i += NTHR) s_bias[i] = b[o0 + i];
    __syncthreads();

    const int lane  = tid & 31;
    const int warp  = tid >> 5;
    const int m_off = (warp % WGM) * WTM;
    const int o_off = (warp / WGM) * 32;

    float acc[MT][NT][4];
    #pragma unroll
    for (int mt = 0; mt < MT; mt++)
        #pragma unroll
        for (int nt = 0; nt < NT; nt++)
            #pragma unroll
            for (int q = 0; q < 4; q++) acc[mt][nt][q] = 0.0f;

    auto copyAB = [&](int t, int s) {
        int k = (t * 32) / C, c0 = (t * 32) % C;
        size_t abase = ((size_t)(s_nei[k] * NN + n0)) * C + c0;
        uint32_t as = sb + s * SSZ;
        constexpr int NA = MTILE * 4;           // 16B transfers per A matrix
        #pragma unroll
        for (int i = 0; i < (NA + NTHR - 1) / NTHR; i++) {
            int lin = tid + i * NTHR;
            if ((NA % NTHR) && lin >= NA) break;
            int row = lin >> 2, seg = lin & 3;
            uint32_t sa = as + swz(row, seg);
            size_t go = abase + (size_t)row * C + seg * 8;
            CP_ASYNC16(sa, Ah + go);
            CP_ASYNC16(sa + AREG, Al + go);
        }
        const __nv_bfloat16* srch = Bhg + (size_t)(blockIdx.y * T + t) * NM * 32;
        const __nv_bfloat16* srcl = Blg + (size_t)(blockIdx.y * T + t) * NM * 32;
        uint32_t bs = sb + s * SSZ + 2 * AREG;
        constexpr int NB = NM * 4;              // 16B transfers per B matrix
        #pragma unroll
        for (int i = 0; i < (NB + NTHR - 1) / NTHR; i++) {
            int lin = tid + i * NTHR;
            if ((NB % NTHR) && lin >= NB) break;
            int row = lin >> 2, seg = lin & 3;
            uint32_t sa = bs + swz(row, seg);
            CP_ASYNC16(sa, srch + lin * 8);
            CP_ASYNC16(sa + BREG, srcl + lin * 8);
        }
        CP_COMMIT();
    };

    auto compute = [&](int s) {
        uint32_t aB = sb + s * SSZ;
        uint32_t bB = aB + 2 * AREG;
        #pragma unroll
        for (int kh = 0; kh < 2; kh++) {
            uint32_t ah[MT][4], al[MT][4];
            uint32_t bh[NT][2], bl[NT][2];
            #pragma unroll
            for (int mt = 0; mt < MT; mt++) {
                int row = m_off + mt * 16 + (lane & 15);
                uint32_t ad = aB + swz(row, kh * 2 + (lane >> 4));
                ldsm4(ad, ah[mt]);
                ldsm4(ad + AREG, al[mt]);
            }
            #pragma unroll
            for (int p = 0; p < 2; p++) {
                int row = o_off + p * 16 + ((lane >> 4) & 1) * 8 + (lane & 7);
                uint32_t bd = bB + swz(row, kh * 2 + ((lane >> 3) & 1));
                uint32_t r[4];
                ldsm4(bd, r);
                bh[p * 2][0] = r[0]; bh[p * 2][1] = r[1];
                bh[p * 2 + 1][0] = r[2]; bh[p * 2 + 1][1] = r[3];
                ldsm4(bd + BREG, r);
                bl[p * 2][0] = r[0]; bl[p * 2][1] = r[1];
                bl[p * 2 + 1][0] = r[2]; bl[p * 2 + 1][1] = r[3];
            }
            // term-major: same-accumulator reuse distance = MT*NT mmas
            #pragma unroll
            for (int mt = 0; mt < MT; mt++)
                #pragma unroll
                for (int nt = 0; nt < NT; nt++) mma_bf(acc[mt][nt], ah[mt], bh[nt]);
            #pragma unroll
            for (int mt = 0; mt < MT; mt++)
                #pragma unroll
                for (int nt = 0; nt < NT; nt++) mma_bf(acc[mt][nt], al[mt], bh[nt]);
            #pragma unroll
            for (int mt = 0; mt < MT; mt++)
                #pragma unroll
                for (int nt = 0; nt < NT; nt++) mma_bf(acc[mt][nt], ah[mt], bl[nt]);
        }
    };

    // 2-stage cp.async pipeline, one __syncthreads per chunk:
    //   wait(copy t) -> sync (publishes stage s; proves stage s^1 compute done)
    //   -> issue copy(t+1) into s^1 -> compute(s)
    copyAB(0, 0);
    for (int t = 0; t < T; t++) {
        int s = t & 1;
        CP_WAIT0();
        __syncthreads();
        if (t + 1 < T) copyAB(t + 1, s ^ 1);
        compute(s);
    }

    // epilogue (acc regs only)
    #pragma unroll
    for (int mt = 0; mt < MT; mt++) {
        int r0 = n0 + m_off + mt * 16 + (lane >> 2);
        #pragma unroll
        for (int nt = 0; nt < NT; nt++) {
            int cl = o_off + nt * 8 + (lane & 3) * 2;
            float b0v = s_bias[cl], b1v = s_bias[cl + 1];
            #pragma unroll
            for (int q = 0; q < 2; q++) {
                int r = r0 + q * 8;
                float vx = acc[mt][nt][q * 2 + 0] + b0v;
                float vy = acc[mt][nt][q * 2 + 1] + b1v;
                if (RELU) { vx = fmaxf(vx, 0.f); vy = fmaxf(vy, 0.f); }
                size_t ei = ((size_t)g * NN + r) * O + o0 + cl;
                if (RRES) {
                    __nv_bfloat162 ph = *(const __nv_bfloat162*)(resH + ei);
                    __nv_bfloat162 pl = *(const __nv_bfloat162*)(resL + ei);
                    vx += __bfloat162float(ph.x) + __bfloat162float(pl.x);
                    vy += __bfloat162float(ph.y) + __bfloat162float(pl.y);
                }
                if (WF32) *(float2*)(outF + ei) = make_float2(vx, vy);
                if (WSPLIT) {
                    float hx = __bfloat162float(__float2bfloat16(vx));
                    float hy = __bfloat162float(__float2bfloat16(vy));
                    *(uint32_t*)(outH + ei) = pk2(hx, hy);
                    *(uint32_t*)(outL + ei) = pk2(vx - hx, vy - hy);
                }
            }
        }
    }
}

// ---------------- epilogue: residual + mean + norms + output ----------------
// out layout: [ feats_inv (N*32) | feats_eqv (N*32*G) ]
__global__ void k_final(const float* __restrict__ feats, float* __restrict__ out) {
    const int n   = blockIdx.x;
    const int tid = threadIdx.x;   // 256 threads
    __shared__ float s_eqv[32][GG];
    __shared__ float s_inv[32];
    __shared__ float s_ng[GG];
    __shared__ float s_ninv;

    for (int idx = tid; idx < 32 * GG; idx += 256) {
        int c = idx / GG;
        int g = idx % GG;
        s_eqv[c][g] = g_E[((size_t)g * NN + n) * 32 + c] + feats[(n * 32 + c) * GG + g];
    }
    __syncthreads();

    if (tid < 32) {
        float sum = 0.0f;
        #pragma unroll 4
        for (int g = 0; g < GG; g++) sum += s_eqv[tid][g];
        s_inv[tid] = sum * (1.0f / GG);
    }
    if (tid >= 64 && tid < 64 + GG) {
        int g = tid - 64;
        float q = 0.0f;
        #pragma unroll
        for (int c = 0; c < 32; c++) { float v = s_eqv[c][g]; q += v * v; }
        s_ng[g] = fmaxf(sqrtf(q), 1e-4f);
    }
    __syncthreads();
    if (tid == 0) {
        float q = 0.0f;
        #pragma unroll
        for (int c = 0; c < 32; c++) q += s_inv[c] * s_inv[c];
        s_ninv = fmaxf(sqrtf(q), 1e-4f);
    }
    __syncthreads();

    if (tid < 32) out[n * 32 + tid] = s_inv[tid] / s_ninv;
    for (int idx = tid; idx < 32 * GG; idx += 256) {
        int c = idx / GG;
        int g = idx % GG;
        out[NN * 32 + (n * 32 + c) * GG + g] = s_eqv[c][g] / s_ng[g];
    }
}

// ---------------- launch (single stream, linear graph) ----------------
extern "C" void kernel_launch(void* const* d_in, const int* in_sizes, int n_in,
                              void* d_out, int out_size) {
    const float* feats = (const float*)d_in[0];
    const int*   nei   = (const int*)  d_in[1];
    const float* W_in  = (const float*)d_in[2];
    const float* b_in  = (const float*)d_in[3];
    const float* W_r1  = (const float*)d_in[4];
    const float* b_r1  = (const float*)d_in[5];
    const float* W_r2  = (const float*)d_in[6];
    const float* b_r2  = (const float*)d_in[7];
    const float* W_out = (const float*)d_in[8];
    const float* b_out = (const float*)d_in[9];
    float* out = (float*)d_out;

    void *pE, *pXh, *pXl, *pHh, *pHl, *pRh, *pRl, *pH2h, *pH2l;
    void *pBh_in, *pBl_in, *pBh_r1, *pBl_r1, *pBh_r2, *pBl_r2, *pBh_out, *pBl_out;
    cudaGetSymbolAddress(&pE,  g_E);
    cudaGetSymbolAddress(&pXh, g_Xh);  cudaGetSymbolAddress(&pXl, g_Xl);
    cudaGetSymbolAddress(&pHh, g_Hh);  cudaGetSymbolAddress(&pHl, g_Hl);
    cudaGetSymbolAddress(&pRh, g_Rh);  cudaGetSymbolAddress(&pRl, g_Rl);
    cudaGetSymbolAddress(&pH2h, g_H2h); cudaGetSymbolAddress(&pH2l, g_H2l);
    cudaGetSymbolAddress(&pBh_in,  g_Bh_in);   cudaGetSymbolAddress(&pBl_in,  g_Bl_in);
    cudaGetSymbolAddress(&pBh_r1,  g_Bh_r1);   cudaGetSymbolAddress(&pBl_r1,  g_Bl_r1);
    cudaGetSymbolAddress(&pBh_r2,  g_Bh_r2);   cudaGetSymbolAddress(&pBl_r2,  g_Bl_r2);
    cudaGetSymbolAddress(&pBh_out, g_Bh_out);  cudaGetSymbolAddress(&pBl_out, g_Bl_out);

    // per-layer configs (race-tested):
    //   in : MTILE=32, NM=128, 5 CTA/SM  (R13)
    //   r1 : MTILE=64, NM=128, 4 CTA/SM  (R10)
    //   r2 : MTILE=32, NM=128, 5 CTA/SM  (R13: 786.5us vs 797.8us)
    //   out: MTILE=64, NM=32,  4 CTA/SM  (halves per-CTA serial depth; 480 CTAs < 1 wave)
    const int SM_IN  = 2 * (2 * 32 * 64 + 2 * 128 * 64);   // 40960
    const int SM_R1  = 2 * (2 * 64 * 64 + 2 * 128 * 64);   // 49152
    const int SM_R2  = SM_IN;                              // 40960
    const int SM_OUT = 2 * (2 * 64 * 64 + 2 * 32 * 64);    // 24576
    cudaFuncSetAttribute((const void*)k_gemm<32, 256, 32, 128, 5, false, false, false, true>,
                         cudaFuncAttributeMaxDynamicSharedMemorySize, SM_IN);
    cudaFuncSetAttribute((const void*)k_gemm<256, 512, 64, 128, 4, true, false, false, true>,
                         cudaFuncAttributeMaxDynamicSharedMemorySize, SM_R1);
    cudaFuncSetAttribute((const void*)k_gemm<512, 256, 32, 128, 5, false, false, true, true>,
                         cudaFuncAttributeMaxDynamicSharedMemorySize, SM_R2);
    cudaFuncSetAttribute((const void*)k_gemm<256, 32, 64, 32, 4, false, true, false, false>,
                         cudaFuncAttributeMaxDynamicSharedMemorySize, SM_OUT);

    // 1. fused prep: feats split + all four weight splits (one launch)
    {
        int total = GG * NN * 32
                  + (256 * 32 + 512 * 256 + 256 * 512 + 32 * 256) * KKN;
        k_prep<<<(total + 255) / 256, 256>>>(feats, W_in, W_r1, W_r2, W_out);
    }
    // 2. in: Hh/Hl = split(comb(X, W_in) + b_in)
    k_gemm<32, 256, 32, 128, 5, false, false, false, true><<<dim3(16, 2, GG), 128, SM_IN>>>(
        (const __nv_bfloat16*)pXh, (const __nv_bfloat16*)pXl,
        (const __nv_bfloat16*)pBh_in, (const __nv_bfloat16*)pBl_in,
        b_in, nei, nullptr, nullptr, nullptr,
        (__nv_bfloat16*)pHh, (__nv_bfloat16*)pHl);
    // 3. r1: Rh/Rl = split(relu(comb(H, W_r1) + b_r1))
    k_gemm<256, 512, 64, 128, 4, true, false, false, true><<<dim3(8, 4, GG), 128, SM_R1>>>(
        (const __nv_bfloat16*)pHh, (const __nv_bfloat16*)pHl,
        (const __nv_bfloat16*)pBh_r1, (const __nv_bfloat16*)pBl_r1,
        b_r1, nei, nullptr, nullptr, nullptr,
        (__nv_bfloat16*)pRh, (__nv_bfloat16*)pRl);
    // 4. r2: H2h/H2l = split((Hh+Hl) + comb(R, W_r2) + b_r2)
    k_gemm<512, 256, 32, 128, 5, false, false, true, true><<<dim3(16, 2, GG), 128, SM_R2>>>(
        (const __nv_bfloat16*)pRh, (const __nv_bfloat16*)pRl,
        (const __nv_bfloat16*)pBh_r2, (const __nv_bfloat16*)pBl_r2,
        b_r2, nei, nullptr,
        (const __nv_bfloat16*)pHh, (const __nv_bfloat16*)pHl,
        (__nv_bfloat16*)pH2h, (__nv_bfloat16*)pH2l);
    // 5. out: E = comb(H2, W_out) + b_out (fp32)
    k_gemm<256, 32, 64, 32, 4, false, true, false, false><<<dim3(8, 1, GG), 128, SM_OUT>>>(
        (const __nv_bfloat16*)pH2h, (const __nv_bfloat16*)pH2l,
        (const __nv_bfloat16*)pBh_out, (const __nv_bfloat16*)pBl_out,
        b_out, nei, (float*)pE, nullptr, nullptr, nullptr, nullptr);
    // 6. final: residual + mean + norms
    k_final<<<NN, 256>>>(feats, out);
}

// round 16
// speedup vs baseline: 1.1748x; 1.0017x over previous
#include <cuda_runtime.h>
#include <cuda_bf16.h>
#include <cstdint>

#define NN  512
#define GG  60
#define KKN 13

// ---------------- scratch (device globals; allocation-free) ----------------
__device__ float g_E [GG * NN * 32];                   // conv_out result fp32
// split activations (bf16 hi/lo), layout [g, n, C]
__device__ __nv_bfloat16 g_Xh[GG * NN * 32],            g_Xl[GG * NN * 32];
__device__ __nv_bfloat16 g_Hh[(size_t)GG * NN * 256],   g_Hl[(size_t)GG * NN * 256];
__device__ __nv_bfloat16 g_Rh[(size_t)GG * NN * 512],   g_Rl[(size_t)GG * NN * 512];
__device__ __nv_bfloat16 g_H2h[(size_t)GG * NN * 256],  g_H2l[(size_t)GG * NN * 256];
// weight chunk images (bf16 hi/lo): [o_blk][chunk t][row o (NM)][32]
__device__ __nv_bfloat16 g_Bh_in [256 * 32  * KKN], g_Bl_in [256 * 32  * KKN];
__device__ __nv_bfloat16 g_Bh_r1 [512 * 256 * KKN], g_Bl_r1 [512 * 256 * KKN];
__device__ __nv_bfloat16 g_Bh_r2 [256 * 512 * KKN], g_Bl_r2 [256 * 512 * KKN];
__device__ __nv_bfloat16 g_Bh_out[32  * 256 * KKN], g_Bl_out[32  * 256 * KKN];

// ---------------- helpers ----------------
__device__ __forceinline__ uint32_t smem_u32(const void* p) {
    uint32_t a;
    asm("{ .reg .u64 t; cvta.to.shared.u64 t, %1; cvt.u32.u64 %0, t; }" : "=r"(a) : "l"(p));
    return a;
}
__device__ __forceinline__ uint32_t pk2(float x, float y) {
    __nv_bfloat162 t = __floats2bfloat162_rn(x, y);
    return *reinterpret_cast<uint32_t*>(&t);
}
// 64B-row swizzle: permute 16B chunk index by (row>>1)&3 -> conflict-free ldmatrix
__device__ __forceinline__ uint32_t swz(int row, int chunk) {
    return (uint32_t)(row * 64 + ((chunk ^ ((row >> 1) & 3)) * 16));
}
__device__ __forceinline__ void ldsm4(uint32_t a, uint32_t r[4]) {
    asm volatile("ldmatrix.sync.aligned.m8n8.x4.shared.b16 {%0,%1,%2,%3}, [%4];"
        : "=r"(r[0]), "=r"(r[1]), "=r"(r[2]), "=r"(r[3]) : "r"(a));
}
__device__ __forceinline__ void mma_bf(float d[4], const uint32_t a[4], const uint32_t b[2]) {
    asm volatile("mma.sync.aligned.m16n8k16.row.col.f32.bf16.bf16.f32 "
        "{%0,%1,%2,%3}, {%4,%5,%6,%7}, {%8,%9}, {%0,%1,%2,%3};"
        : "+f"(d[0]), "+f"(d[1]), "+f"(d[2]), "+f"(d[3])
        : "r"(a[0]), "r"(a[1]), "r"(a[2]), "r"(a[3]), "r"(b[0]), "r"(b[1]));
}
#define CP_ASYNC16(saddr, gptr) \
    asm volatile("cp.async.cg.shared.global [%0], [%1], 16;" :: "r"(saddr), "l"(gptr) : "memory")
#define CP_COMMIT()  asm volatile("cp.async.commit_group;" ::: "memory")
#define CP_WAIT0()   asm volatile("cp.async.wait_group 0;" ::: "memory")

// ---------------- fused prep: feats split + all four weight splits ----------------
__global__ void k_prep(const float* __restrict__ feats,
                       const float* __restrict__ W0, const float* __restrict__ W1,
                       const float* __restrict__ W2, const float* __restrict__ W3) {
    int idx = blockIdx.x * blockDim.x + threadIdx.x;
    const int fTot = GG * NN * 32;
    if (idx < fTot) {
        int g = idx / (NN * 32);
        int r = idx % (NN * 32);
        int n = r / 32, c = r % 32;
        float v = feats[(n * 32 + c) * GG + g];
        __nv_bfloat16 h = __float2bfloat16(v);
        g_Xh[idx] = h;
        g_Xl[idx] = __float2bfloat16(v - __bfloat162float(h));
        return;
    }
    int wi = idx - fTot;
    const int s0 = 256 * 32 * KKN;          // in
    const int s1 = 512 * 256 * KKN;         // r1
    const int s2 = 256 * 512 * KKN;         // r2
    const int s3 = 32 * 256 * KKN;          // out
    const float* W; __nv_bfloat16 *Wh, *Wl; int C, NM, li;
    if (wi < s0)                { W = W0; Wh = g_Bh_in;  Wl = g_Bl_in;  C = 32;  NM = 128; li = wi; }
    else if (wi < s0 + s1)      { W = W1; Wh = g_Bh_r1;  Wl = g_Bl_r1;  C = 256; NM = 128; li = wi - s0; }
    else if (wi < s0 + s1 + s2) { W = W2; Wh = g_Bh_r2;  Wl = g_Bl_r2;  C = 512; NM = 128; li = wi - s0 - s1; }
    else if (wi < s0 + s1 + s2 + s3)
                                { W = W3; Wh = g_Bh_out; Wl = g_Bl_out; C = 256; NM = 32;  li = wi - s0 - s1 - s2; }
    else return;
    const int CK = C * KKN;
    int o = li / CK, ck = li % CK;
    int k = ck / C, c = ck % C;
    float v = W[(o * C + c) * KKN + k];
    __nv_bfloat16 h = __float2bfloat16(v);
    int T = CK / 32, t = ck / 32, j = ck % 32;
    int ob = o / NM, row = o % NM;
    size_t di = ((size_t)(ob * T + t) * NM + row) * 32 + j;
    Wh[di] = h;
    Wl[di] = __float2bfloat16(v - __bfloat162float(h));
}

// ---------------- bf16x3 mma.sync gather-GEMM (pre-split operands) ----------------
// D[n,o] = sum_{k,c} X[nei[g,k]][n][c] * W[o][k*C+c] ; epilogue per flags
// CTA tile: MTILE x NM, 4 warps (128 threads), MAXB CTAs/SM.
// 2-stage cp.async pipeline, 1 sync/chunk. (Per-layer configs race-tested R10/R13.)
template <int C, int O, int MTILE, int NM, int MAXB, bool RELU, bool WF32, bool RRES, bool WSPLIT>
__global__ void __launch_bounds__(128, MAXB)
k_gemm(const __nv_bfloat16* __restrict__ Ah, const __nv_bfloat16* __restrict__ Al,
       const __nv_bfloat16* __restrict__ Bhg, const __nv_bfloat16* __restrict__ Blg,
       const float* __restrict__ b, const int* __restrict__ nei,
       float* __restrict__ outF,
       const __nv_bfloat16* __restrict__ resH, const __nv_bfloat16* __restrict__ resL,
       __nv_bfloat16* __restrict__ outH, __nv_bfloat16* __restrict__ outL) {
    constexpr int NTHR = 128;
    constexpr int NWARP = 4;
    constexpr int CK  = C * KKN;
    constexpr int T   = CK / 32;
    constexpr int WGN = (NM / 32 < NWARP) ? NM / 32 : NWARP;   // warps along o
    constexpr int WGM = NWARP / WGN;    // warps along n
    constexpr int WTM = MTILE / WGM;    // warp tile m
    constexpr int MT  = WTM / 16;
    static_assert(WTM >= 16, "warp tile too small");
    constexpr int NT  = 4;              // warp tile n = 32
    constexpr int AREG = MTILE * 64;    // one A matrix region (MTILE rows x 64B, swizzled)
    constexpr int BREG = NM * 64;
    constexpr int SSZ  = 2 * AREG + 2 * BREG;

    extern __shared__ char smem[];
    __shared__ int   s_nei[KKN];
    __shared__ float s_bias[NM];

    const int tid = threadIdx.x;
    const int g   = blockIdx.z;
    const int n0  = blockIdx.x * MTILE;
    const int o0  = blockIdx.y * NM;
    const uint32_t sb = smem_u32(smem);

    if (tid < KKN) s_nei[tid] = nei[g * KKN + tid];
    for (int i = tid; i < NM; i += NTHR) s_bias[i] = b[o0 + i];
    __syncthreads();

    const int lane  = tid & 31;
    const int warp  = tid >> 5;
    const int m_off = (warp % WGM) * WTM;
    const int o_off = (warp / WGM) * 32;

    float acc[MT][NT][4];
    #pragma unroll
    for (int mt = 0; mt < MT; mt++)
        #pragma unroll
        for (int nt = 0; nt < NT; nt++)
            #pragma unroll
            for (int q = 0; q < 4; q++) acc[mt][nt][q] = 0.0f;

    auto copyAB = [&](int t, int s) {
        int k = (t * 32) / C, c0 = (t * 32) % C;
        size_t abase = ((size_t)(s_nei[k] * NN + n0)) * C + c0;
        uint32_t as = sb + s * SSZ;
        constexpr int NA = MTILE * 4;           // 16B transfers per A matrix
        #pragma unroll
        for (int i = 0; i < (NA + NTHR - 1) / NTHR; i++) {
            int lin = tid + i * NTHR;
            if ((NA % NTHR) && lin >= NA) break;
            int row = lin >> 2, seg = lin & 3;
            uint32_t sa = as + swz(row, seg);
            size_t go = abase + (size_t)row * C + seg * 8;
            CP_ASYNC16(sa, Ah + go);
            CP_ASYNC16(sa + AREG, Al + go);
        }
        const __nv_bfloat16* srch = Bhg + (size_t)(blockIdx.y * T + t) * NM * 32;
        const __nv_bfloat16* srcl = Blg + (size_t)(blockIdx.y * T + t) * NM * 32;
        uint32_t bs = sb + s * SSZ + 2 * AREG;
        constexpr int NB = NM * 4;              // 16B transfers per B matrix
        #pragma unroll
        for (int i = 0; i < (NB + NTHR - 1) / NTHR; i++) {
            int lin = tid + i * NTHR;
            if ((NB % NTHR) && lin >= NB) break;
            int row = lin >> 2, seg = lin & 3;
            uint32_t sa = bs + swz(row, seg);
            CP_ASYNC16(sa, srch + lin * 8);
            CP_ASYNC16(sa + BREG, srcl + lin * 8);
        }
        CP_COMMIT();
    };

    auto compute = [&](int s) {
        uint32_t aB = sb + s * SSZ;
        uint32_t bB = aB + 2 * AREG;
        #pragma unroll
        for (int kh = 0; kh < 2; kh++) {
            uint32_t ah[MT][4], al[MT][4];
            uint32_t bh[NT][2], bl[NT][2];
            #pragma unroll
            for (int mt = 0; mt < MT; mt++) {
                int row = m_off + mt * 16 + (lane & 15);
                uint32_t ad = aB + swz(row, kh * 2 + (lane >> 4));
                ldsm4(ad, ah[mt]);
                ldsm4(ad + AREG, al[mt]);
            }
            #pragma unroll
            for (int p = 0; p < 2; p++) {
                int row = o_off + p * 16 + ((lane >> 4) & 1) * 8 + (lane & 7);
                uint32_t bd = bB + swz(row, kh * 2 + ((lane >> 3) & 1));
                uint32_t r[4];
                ldsm4(bd, r);
                bh[p * 2][0] = r[0]; bh[p * 2][1] = r[1];
                bh[p * 2 + 1][0] = r[2]; bh[p * 2 + 1][1] = r[3];
                ldsm4(bd + BREG, r);
                bl[p * 2][0] = r[0]; bl[p * 2][1] = r[1];
                bl[p * 2 + 1][0] = r[2]; bl[p * 2 + 1][1] = r[3];
            }
            // term-major: same-accumulator reuse distance = MT*NT mmas
            #pragma unroll
            for (int mt = 0; mt < MT; mt++)
                #pragma unroll
                for (int nt = 0; nt < NT; nt++) mma_bf(acc[mt][nt], ah[mt], bh[nt]);
            #pragma unroll
            for (int mt = 0; mt < MT; mt++)
                #pragma unroll
                for (int nt = 0; nt < NT; nt++) mma_bf(acc[mt][nt], al[mt], bh[nt]);
            #pragma unroll
            for (int mt = 0; mt < MT; mt++)
                #pragma unroll
                for (int nt = 0; nt < NT; nt++) mma_bf(acc[mt][nt], ah[mt], bl[nt]);
        }
    };

    // 2-stage cp.async pipeline, one __syncthreads per chunk:
    //   wait(copy t) -> sync (publishes stage s; proves stage s^1 compute done)
    //   -> issue copy(t+1) into s^1 -> compute(s)
    copyAB(0, 0);
    for (int t = 0; t < T; t++) {
        int s = t & 1;
        CP_WAIT0();
        __syncthreads();
        if (t + 1 < T) copyAB(t + 1, s ^ 1);
        compute(s);
    }

    // epilogue (acc regs only)
    #pragma unroll
    for (int mt = 0; mt < MT; mt++) {
        int r0 = n0 + m_off + mt * 16 + (lane >> 2);
        #pragma unroll
        for (int nt = 0; nt < NT; nt++) {
            int cl = o_off + nt * 8 + (lane & 3) * 2;
            float b0v = s_bias[cl], b1v = s_bias[cl + 1];
            #pragma unroll
            for (int q = 0; q < 2; q++) {
                int r = r0 + q * 8;
                float vx = acc[mt][nt][q * 2 + 0] + b0v;
                float vy = acc[mt][nt][q * 2 + 1] + b1v;
                if (RELU) { vx = fmaxf(vx, 0.f); vy = fmaxf(vy, 0.f); }
                size_t ei = ((size_t)g * NN + r) * O + o0 + cl;
                if (RRES) {
                    __nv_bfloat162 ph = *(const __nv_bfloat162*)(resH + ei);
                    __nv_bfloat162 pl = *(const __nv_bfloat162*)(resL + ei);
                    vx += __bfloat162float(ph.x) + __bfloat162float(pl.x);
                    vy += __bfloat162float(ph.y) + __bfloat162float(pl.y);
                }
                if (WF32) *(float2*)(outF + ei) = make_float2(vx, vy);
                if (WSPLIT) {
                    float hx = __bfloat162float(__float2bfloat16(vx));
                    float hy = __bfloat162float(__float2bfloat16(vy));
                    *(uint32_t*)(outH + ei) = pk2(hx, hy);
                    *(uint32_t*)(outL + ei) = pk2(vx - hx, vy - hy);
                }
            }
        }
    }
}

// ---------------- epilogue: residual + mean + norms + output ----------------
// out layout: [ feats_inv (N*32) | feats_eqv (N*32*G) ]
__global__ void k_final(const float* __restrict__ feats, float* __restrict__ out) {
    const int n   = blockIdx.x;
    const int tid = threadIdx.x;   // 256 threads
    __shared__ float s_eqv[32][GG];
    __shared__ float s_inv[32];
    __shared__ float s_ng[GG];
    __shared__ float s_ninv;

    for (int idx = tid; idx < 32 * GG; idx += 256) {
        int c = idx / GG;
        int g = idx % GG;
        s_eqv[c][g] = g_E[((size_t)g * NN + n) * 32 + c] + feats[(n * 32 + c) * GG + g];
    }
    __syncthreads();

    if (tid < 32) {
        float sum = 0.0f;
        #pragma unroll 4
        for (int g = 0; g < GG; g++) sum += s_eqv[tid][g];
        s_inv[tid] = sum * (1.0f / GG);
    }
    if (tid >= 64 && tid < 64 + GG) {
        int g = tid - 64;
        float q = 0.0f;
        #pragma unroll
        for (int c = 0; c < 32; c++) { float v = s_eqv[c][g]; q += v * v; }
        s_ng[g] = fmaxf(sqrtf(q), 1e-4f);
    }
    __syncthreads();
    if (tid == 0) {
        float q = 0.0f;
        #pragma unroll
        for (int c = 0; c < 32; c++) q += s_inv[c] * s_inv[c];
        s_ninv = fmaxf(sqrtf(q), 1e-4f);
    }
    __syncthreads();

    if (tid < 32) out[n * 32 + tid] = s_inv[tid] / s_ninv;
    for (int idx = tid; idx < 32 * GG; idx += 256) {
        int c = idx / GG;
        int g = idx % GG;
        out[NN * 32 + (n * 32 + c) * GG + g] = s_eqv[c][g] / s_ng[g];
    }
}

// ---------------- launch (single stream, linear graph) ----------------
extern "C" void kernel_launch(void* const* d_in, const int* in_sizes, int n_in,
                              void* d_out, int out_size) {
    const float* feats = (const float*)d_in[0];
    const int*   nei   = (const int*)  d_in[1];
    const float* W_in  = (const float*)d_in[2];
    const float* b_in  = (const float*)d_in[3];
    const float* W_r1  = (const float*)d_in[4];
    const float* b_r1  = (const float*)d_in[5];
    const float* W_r2  = (const float*)d_in[6];
    const float* b_r2  = (const float*)d_in[7];
    const float* W_out = (const float*)d_in[8];
    const float* b_out = (const float*)d_in[9];
    float* out = (float*)d_out;

    void *pE, *pXh, *pXl, *pHh, *pHl, *pRh, *pRl, *pH2h, *pH2l;
    void *pBh_in, *pBl_in, *pBh_r1, *pBl_r1, *pBh_r2, *pBl_r2, *pBh_out, *pBl_out;
    cudaGetSymbolAddress(&pE,  g_E);
    cudaGetSymbolAddress(&pXh, g_Xh);  cudaGetSymbolAddress(&pXl, g_Xl);
    cudaGetSymbolAddress(&pHh, g_Hh);  cudaGetSymbolAddress(&pHl, g_Hl);
    cudaGetSymbolAddress(&pRh, g_Rh);  cudaGetSymbolAddress(&pRl, g_Rl);
    cudaGetSymbolAddress(&pH2h, g_H2h); cudaGetSymbolAddress(&pH2l, g_H2l);
    cudaGetSymbolAddress(&pBh_in,  g_Bh_in);   cudaGetSymbolAddress(&pBl_in,  g_Bl_in);
    cudaGetSymbolAddress(&pBh_r1,  g_Bh_r1);   cudaGetSymbolAddress(&pBl_r1,  g_Bl_r1);
    cudaGetSymbolAddress(&pBh_r2,  g_Bh_r2);   cudaGetSymbolAddress(&pBl_r2,  g_Bl_r2);
    cudaGetSymbolAddress(&pBh_out, g_Bh_out);  cudaGetSymbolAddress(&pBl_out, g_Bl_out);

    // per-layer configs (race-tested):
    //   in : MTILE=32, NM=128, 5 CTA/SM  (R13)
    //   r1 : MTILE=64, NM=128, 4 CTA/SM  (R10)
    //   r2 : MTILE=32, NM=128, 5 CTA/SM  (R13: 786.5us vs 797.8us)
    //   out: MTILE=64, NM=32,  4 CTA/SM  (halves per-CTA serial depth; 480 CTAs < 1 wave)
    const int SM_IN  = 2 * (2 * 32 * 64 + 2 * 128 * 64);   // 40960
    const int SM_R1  = 2 * (2 * 64 * 64 + 2 * 128 * 64);   // 49152
    const int SM_R2  = SM_IN;                              // 40960
    const int SM_OUT = 2 * (2 * 64 * 64 + 2 * 32 * 64);    // 24576
    cudaFuncSetAttribute((const void*)k_gemm<32, 256, 32, 128, 5, false, false, false, true>,
                         cudaFuncAttributeMaxDynamicSharedMemorySize, SM_IN);
    cudaFuncSetAttribute((const void*)k_gemm<256, 512, 64, 128, 4, true, false, false, true>,
                         cudaFuncAttributeMaxDynamicSharedMemorySize, SM_R1);
    cudaFuncSetAttribute((const void*)k_gemm<512, 256, 32, 128, 5, false, false, true, true>,
                         cudaFuncAttributeMaxDynamicSharedMemorySize, SM_R2);
    cudaFuncSetAttribute((const void*)k_gemm<256, 32, 64, 32, 4, false, true, false, false>,
                         cudaFuncAttributeMaxDynamicSharedMemorySize, SM_OUT);

    // 1. fused prep: feats split + all four weight splits (one launch)
    {
        int total = GG * NN * 32
                  + (256 * 32 + 512 * 256 + 256 * 512 + 32 * 256) * KKN;
        k_prep<<<(total + 255) / 256, 256>>>(feats, W_in, W_r1, W_r2, W_out);
    }
    // 2. in: Hh/Hl = split(comb(X, W_in) + b_in)
    k_gemm<32, 256, 32, 128, 5, false, false, false, true><<<dim3(16, 2, GG), 128, SM_IN>>>(
        (const __nv_bfloat16*)pXh, (const __nv_bfloat16*)pXl,
        (const __nv_bfloat16*)pBh_in, (const __nv_bfloat16*)pBl_in,
        b_in, nei, nullptr, nullptr, nullptr,
        (__nv_bfloat16*)pHh, (__nv_bfloat16*)pHl);
    // 3. r1: Rh/Rl = split(relu(comb(H, W_r1) + b_r1))
    k_gemm<256, 512, 64, 128, 4, true, false, false, true><<<dim3(8, 4, GG), 128, SM_R1>>>(
        (const __nv_bfloat16*)pHh, (const __nv_bfloat16*)pHl,
        (const __nv_bfloat16*)pBh_r1, (const __nv_bfloat16*)pBl_r1,
        b_r1, nei, nullptr, nullptr, nullptr,
        (__nv_bfloat16*)pRh, (__nv_bfloat16*)pRl);
    // 4. r2: H2h/H2l = split((Hh+Hl) + comb(R, W_r2) + b_r2)
    k_gemm<512, 256, 32, 128, 5, false, false, true, true><<<dim3(16, 2, GG), 128, SM_R2>>>(
        (const __nv_bfloat16*)pRh, (const __nv_bfloat16*)pRl,
        (const __nv_bfloat16*)pBh_r2, (const __nv_bfloat16*)pBl_r2,
        b_r2, nei, nullptr,
        (const __nv_bfloat16*)pHh, (const __nv_bfloat16*)pHl,
        (__nv_bfloat16*)pH2h, (__nv_bfloat16*)pH2l);
    // 5. out: E = comb(H2, W_out) + b_out (fp32)
    k_gemm<256, 32, 64, 32, 4, false, true, false, false><<<dim3(8, 1, GG), 128, SM_OUT>>>(
        (const __nv_bfloat16*)pH2h, (const __nv_bfloat16*)pH2l,
        (const __nv_bfloat16*)pBh_out, (const __nv_bfloat16*)pBl_out,
        b_out, nei, (float*)pE, nullptr, nullptr, nullptr, nullptr);
    // 6. final: residual + mean + norms
    k_final<<<NN, 256>>>(feats, out);
}